// round 2
// baseline (speedup 1.0000x reference)
#include <cuda_runtime.h>
#include <cuda_bf16.h>
#include <math.h>

// Problem constants
#define BB 4
#define LL 512
#define DD 768
#define HH 12
#define MM 48
#define EE 32
#define PP 512
#define RR 97
#define NBK 12      // D / 64 group blocks
#define KCLAS 49152 // D * 64

// ---------------- scratch (device globals; allocation-free) ----------------
__device__ float g_att_sum[BB*LL*LL];       // (B,L,L)
__device__ float g_mention[BB*MM*DD];       // (B,M,D)
__device__ float g_tmp1[BB*MM*LL];          // mention_map @ att_sum
__device__ float g_matt[BB*MM*MM];          // mention_att
__device__ float g_eatt[BB*EE*MM];          // entity_att
__device__ float g_emtok[BB*EE*LL];         // em_tok (normalized in place)
__device__ float g_entatt[BB*HH*EE*LL];     // ent_att (B,H,E,L)
__device__ float g_hatt[BB*PP*MM];          // normalized h_att
__device__ float g_tatt[BB*PP*MM];          // normalized t_att
__device__ float g_ctx[BB*PP*LL];           // normalized ctx_att * mask
__device__ float g_h[BB*PP*DD];
__device__ float g_t[BB*PP*DD];
__device__ float g_cinfo[BB*PP*DD];
__device__ float g_hf[BB*PP*DD];            // final tanh'd h
__device__ float g_tf[BB*PP*DD];
__device__ float g_part[NBK*BB*PP*RR];      // classifier partials per n-block

// ---------------- small kernels ----------------
__global__ void att_sum_k(const float* __restrict__ att, float* __restrict__ out)
{
    int idx = blockIdx.x * 256 + threadIdx.x;
    if (idx >= BB*LL*LL) return;
    int b  = idx >> 18;               // / (512*512)
    int lm = idx & (LL*LL - 1);
    const float* p = att + (size_t)b*HH*LL*LL + lm;
    float s = 0.f;
#pragma unroll
    for (int h = 0; h < HH; ++h) s += p[(size_t)h*LL*LL];
    out[idx] = s;
}

// normalize B*E rows of length L in place (em_tok)
__global__ void rownorm_k(float* __restrict__ x)
{
    int row = blockIdx.x;             // 0..B*E-1
    float* p = x + (size_t)row * LL;
    int t = threadIdx.x;              // 256
    float v0 = p[t], v1 = p[t + 256];
    __shared__ float sm[256];
    sm[t] = v0 + v1; __syncthreads();
    for (int o = 128; o > 0; o >>= 1) { if (t < o) sm[t] += sm[t + o]; __syncthreads(); }
    float inv = 1.f / (sm[0] + 1e-30f);
    p[t] = v0 * inv; p[t + 256] = v1 * inv;
}

// per-(b,p): masked, normalized h_att / t_att (length 48)
__global__ void pair_att_k(const int* __restrict__ hts,
                           const float* __restrict__ emap,
                           const float* __restrict__ eatt,
                           float* __restrict__ hattO, float* __restrict__ tattO)
{
    int bp = blockIdx.x;              // 0..B*P-1
    int b  = bp >> 9;
    int hi = hts[(size_t)bp*2], ti = hts[(size_t)bp*2 + 1];
    float mask = (hi + ti != 0) ? 1.f : 0.f;
    int t = threadIdx.x;              // 64
    float ha = 0.f, ta = 0.f;
    if (t < MM) {
        float hm = emap[((size_t)b*EE + hi)*MM + t] * mask;  // h_mask
        float tm = emap[((size_t)b*EE + ti)*MM + t] * mask;  // t_mask
        ha = eatt[((size_t)b*EE + hi)*MM + t] * tm;          // h_att
        ta = eatt[((size_t)b*EE + ti)*MM + t] * hm;          // t_att
    }
    __shared__ float smh[64], smt[64];
    smh[t] = ha; smt[t] = ta; __syncthreads();
    for (int o = 32; o > 0; o >>= 1) {
        if (t < o) { smh[t] += smh[t + o]; smt[t] += smt[t + o]; }
        __syncthreads();
    }
    float invh = 1.f / (smh[0] + 1e-30f);
    float invt = 1.f / (smt[0] + 1e-30f);
    if (t < MM) {
        hattO[(size_t)bp*MM + t] = ha * invh;
        tattO[(size_t)bp*MM + t] = ta * invt;
    }
}

// per-(b,p): ctx_att[m] = sum_h entA[b,h,hi,m]*entA[b,h,ti,m], normalized, * mask
__global__ void ctx_k(const int* __restrict__ hts,
                      const float* __restrict__ entatt,
                      float* __restrict__ ctxO)
{
    int bp = blockIdx.x; int b = bp >> 9;
    int hi = hts[(size_t)bp*2], ti = hts[(size_t)bp*2 + 1];
    float mask = (hi + ti != 0) ? 1.f : 0.f;
    int t = threadIdx.x;              // 256
    const float* base = entatt + (size_t)b*HH*EE*LL;
    float v0 = 0.f, v1 = 0.f;
#pragma unroll
    for (int h = 0; h < HH; ++h) {
        const float* ph = base + ((size_t)h*EE + hi)*LL;
        const float* pt = base + ((size_t)h*EE + ti)*LL;
        v0 += ph[t]       * pt[t];
        v1 += ph[t + 256] * pt[t + 256];
    }
    __shared__ float sm[256];
    sm[t] = v0 + v1; __syncthreads();
    for (int o = 128; o > 0; o >>= 1) { if (t < o) sm[t] += sm[t + o]; __syncthreads(); }
    float inv = mask / (sm[0] + 1e-30f);
    ctxO[(size_t)bp*LL + t]       = v0 * inv;
    ctxO[(size_t)bp*LL + t + 256] = v1 * inv;
}

// ---------------- generic tiled GEMM ----------------
// C[M,N] (+)= A[M,K] * B[K,N]  (TB=false)  or  A[M,K] * B[N,K]^T (TB=true)
// Optional bias[n], accumulate-into-C, tanh epilogue.
// Per-z offsets: ptr += (z/div) * stride.
template<bool TB, bool ACC, bool DOTANH, bool HASBIAS>
__global__ __launch_bounds__(256)
void gemm_k(const float* __restrict__ Ag, const float* __restrict__ Bg,
            const float* __restrict__ bias, float* __restrict__ Cg,
            int M, int N, int K,
            long long sA, long long sB, long long sC,
            int dA, int dB, int dC)
{
    const int BM = 64, BN = 64, BK = 16;
    int z = blockIdx.z;
    const float* A  = Ag + (long long)(z / dA) * sA;
    const float* Bp = Bg + (long long)(z / dB) * sB;
    float*       C  = Cg + (long long)(z / dC) * sC;
    int row0 = blockIdx.y * BM;
    int col0 = blockIdx.x * BN;

    __shared__ float As[BK][BM + 1];
    __shared__ float Bs[BK][BN + 1];

    int tid = threadIdx.x;
    int tx = tid & 15, ty = tid >> 4;
    float acc[4][4] = {};

    for (int k0 = 0; k0 < K; k0 += BK) {
#pragma unroll
        for (int r = 0; r < 4; ++r) {
            int idx = tid + r * 256;              // 0..1023
            int m = idx >> 4, k = idx & 15;
            float v = 0.f;
            if (row0 + m < M) v = A[(size_t)(row0 + m) * K + k0 + k];
            As[k][m] = v;
        }
        if (!TB) {
#pragma unroll
            for (int r = 0; r < 4; ++r) {
                int idx = tid + r * 256;
                int k = idx >> 6, n = idx & 63;
                float v = 0.f;
                if (col0 + n < N) v = Bp[(size_t)(k0 + k) * N + col0 + n];
                Bs[k][n] = v;
            }
        } else {
#pragma unroll
            for (int r = 0; r < 4; ++r) {
                int idx = tid + r * 256;
                int n = idx >> 4, k = idx & 15;
                float v = 0.f;
                if (col0 + n < N) v = Bp[(size_t)(col0 + n) * K + k0 + k];
                Bs[k][n] = v;
            }
        }
        __syncthreads();
#pragma unroll
        for (int k = 0; k < BK; ++k) {
            float a[4], bb[4];
#pragma unroll
            for (int i = 0; i < 4; ++i) a[i]  = As[k][ty * 4 + i];
#pragma unroll
            for (int j = 0; j < 4; ++j) bb[j] = Bs[k][tx * 4 + j];
#pragma unroll
            for (int i = 0; i < 4; ++i)
#pragma unroll
                for (int j = 0; j < 4; ++j) acc[i][j] += a[i] * bb[j];
        }
        __syncthreads();
    }

#pragma unroll
    for (int i = 0; i < 4; ++i) {
        int m = row0 + ty * 4 + i;
        if (m >= M) continue;
#pragma unroll
        for (int j = 0; j < 4; ++j) {
            int n = col0 + tx * 4 + j;
            if (n >= N) continue;
            float v = acc[i][j];
            if (HASBIAS) v += bias[n];
            if (ACC)     v += C[(size_t)m * N + n];
            if (DOTANH)  v = tanhf(v);
            C[(size_t)m * N + n] = v;
        }
    }
}

// ---------------- classifier (group bilinear + clasW) ----------------
// out[p,r] += sum_{i,j} h[p, n*64+i] * t[p, n*64+j] * W[r, n*4096 + i*64 + j]
// grid: x = pair tile (64 pairs), y = n (0..11); partials per n (deterministic).
#define CLAS_SMEM ((64*64 + 64*65 + 64*113) * 4)
__global__ __launch_bounds__(256)
void clas_k(const float* __restrict__ Hf, const float* __restrict__ Tf,
            const float* __restrict__ W, float* __restrict__ part)
{
    extern __shared__ float sh[];
    float* hs = sh;                       // [64][64]
    float* ts = sh + 64*64;               // [64][65]
    float* ws = sh + 64*64 + 64*65;       // [64][113]  (j-major, r padded to 112)
    const int n  = blockIdx.y;
    const int p0 = blockIdx.x * 64;
    int tid = threadIdx.x;                // 256

    for (int v = tid; v < 4096; v += 256) {
        int p = v >> 6, i = v & 63;
        size_t off = (size_t)(p0 + p) * DD + n * 64 + i;
        hs[p * 64 + i] = Hf[off];
        ts[p * 65 + i] = Tf[off];
    }
    // zero-pad r = 97..112 once
    for (int v = tid; v < 16 * 64; v += 256) {
        int j = v >> 4, r = 97 + (v & 15);
        ws[j * 113 + r] = 0.f;
    }

    float acc[4][7];
#pragma unroll
    for (int i = 0; i < 4; ++i)
#pragma unroll
        for (int j = 0; j < 7; ++j) acc[i][j] = 0.f;

    int tx = tid & 15, ty = tid >> 4;

    for (int i = 0; i < 64; ++i) {
        __syncthreads();
        // stage W slice: ws[j][r] = W[r, n*4096 + i*64 + j]
        for (int v = tid; v < RR * 64; v += 256) {
            int r = v >> 6, j = v & 63;
            ws[j * 113 + r] = W[(size_t)r * KCLAS + n * 4096 + i * 64 + j];
        }
        __syncthreads();
        float hv[4];
#pragma unroll
        for (int pp = 0; pp < 4; ++pp) hv[pp] = hs[(ty * 4 + pp) * 64 + i];
#pragma unroll 4
        for (int j = 0; j < 64; ++j) {
            float bb[7];
#pragma unroll
            for (int rr = 0; rr < 7; ++rr) bb[rr] = ws[j * 113 + tx * 7 + rr];
#pragma unroll
            for (int pp = 0; pp < 4; ++pp) {
                float a = hv[pp] * ts[(ty * 4 + pp) * 65 + j];
#pragma unroll
                for (int rr = 0; rr < 7; ++rr) acc[pp][rr] += a * bb[rr];
            }
        }
    }

    float* po = part + (size_t)n * (BB * PP * RR);
#pragma unroll
    for (int pp = 0; pp < 4; ++pp) {
        int p = p0 + ty * 4 + pp;
#pragma unroll
        for (int rr = 0; rr < 7; ++rr) {
            int r = tx * 7 + rr;
            if (r < RR) po[(size_t)p * RR + r] = acc[pp][rr];
        }
    }
}

__global__ void clas_red_k(const float* __restrict__ part,
                           const float* __restrict__ clasb,
                           float* __restrict__ out)
{
    int idx = blockIdx.x * 256 + threadIdx.x;
    if (idx >= BB * PP * RR) return;
    int r = idx % RR;
    float s = clasb[r];
#pragma unroll
    for (int nn = 0; nn < NBK; ++nn) s += part[(size_t)nn * (BB * PP * RR) + idx];
    out[idx] = s;
}

// ---------------- host ----------------
extern "C" void kernel_launch(void* const* d_in, const int* in_sizes, int n_in,
                              void* d_out, int out_size)
{
    const float* context   = (const float*)d_in[0];
    const float* attention = (const float*)d_in[1];
    const float* mmap      = (const float*)d_in[2];
    const float* emap      = (const float*)d_in[3];
    const int*   hts       = (const int*)d_in[4];   // int64 in ref, int32 in harness
    const float* hW   = (const float*)d_in[5];
    const float* hb   = (const float*)d_in[6];
    const float* tW   = (const float*)d_in[7];
    const float* tb   = (const float*)d_in[8];
    const float* hcW  = (const float*)d_in[9];
    const float* hcb  = (const float*)d_in[10];
    const float* tcW  = (const float*)d_in[11];
    const float* tcb  = (const float*)d_in[12];
    const float* clasW = (const float*)d_in[13];
    const float* clasb = (const float*)d_in[14];
    float* out = (float*)d_out;

    float *att_sum, *mention, *tmp1, *matt, *eatt, *emtok, *entatt;
    float *hatt, *tatt, *ctx, *h_, *t_, *cinfo, *hf, *tf, *part;
    cudaGetSymbolAddress((void**)&att_sum, g_att_sum);
    cudaGetSymbolAddress((void**)&mention, g_mention);
    cudaGetSymbolAddress((void**)&tmp1,    g_tmp1);
    cudaGetSymbolAddress((void**)&matt,    g_matt);
    cudaGetSymbolAddress((void**)&eatt,    g_eatt);
    cudaGetSymbolAddress((void**)&emtok,   g_emtok);
    cudaGetSymbolAddress((void**)&entatt,  g_entatt);
    cudaGetSymbolAddress((void**)&hatt,    g_hatt);
    cudaGetSymbolAddress((void**)&tatt,    g_tatt);
    cudaGetSymbolAddress((void**)&ctx,     g_ctx);
    cudaGetSymbolAddress((void**)&h_,      g_h);
    cudaGetSymbolAddress((void**)&t_,      g_t);
    cudaGetSymbolAddress((void**)&cinfo,   g_cinfo);
    cudaGetSymbolAddress((void**)&hf,      g_hf);
    cudaGetSymbolAddress((void**)&tf,      g_tf);
    cudaGetSymbolAddress((void**)&part,    g_part);

    // 1) att_sum = attention.sum(h)
    att_sum_k<<<(BB*LL*LL + 255)/256, 256>>>(attention, att_sum);

    // 2) mention = mention_map @ context   (per b: 48x768, K=512)
    gemm_k<false,false,false,false><<<dim3(12,1,BB),256>>>(
        mmap, context, nullptr, mention, MM, DD, LL,
        (long long)MM*LL, (long long)LL*DD, (long long)MM*DD, 1,1,1);

    // 3) tmp1 = mention_map @ att_sum   (48x512, K=512)
    gemm_k<false,false,false,false><<<dim3(8,1,BB),256>>>(
        mmap, att_sum, nullptr, tmp1, MM, LL, LL,
        (long long)MM*LL, (long long)LL*LL, (long long)MM*LL, 1,1,1);

    // 4) mention_att = tmp1 @ mention_map^T   (48x48, K=512)
    gemm_k<true,false,false,false><<<dim3(1,1,BB),256>>>(
        tmp1, mmap, nullptr, matt, MM, MM, LL,
        (long long)MM*LL, (long long)MM*LL, (long long)MM*MM, 1,1,1);

    // 5) entity_att = entity_map @ mention_att   (32x48, K=48)
    gemm_k<false,false,false,false><<<dim3(1,1,BB),256>>>(
        emap, matt, nullptr, eatt, EE, MM, MM,
        (long long)EE*MM, (long long)MM*MM, (long long)EE*MM, 1,1,1);

    // 6) em_tok = entity_map @ mention_map, then row-normalize   (32x512, K=48)
    gemm_k<false,false,false,false><<<dim3(8,1,BB),256>>>(
        emap, mmap, nullptr, emtok, EE, LL, MM,
        (long long)EE*MM, (long long)MM*LL, (long long)EE*LL, 1,1,1);
    rownorm_k<<<BB*EE, 256>>>(emtok);

    // 7) ent_att[b,h] = em_tok[b] @ attention[b,h]   (32x512, K=512), z=b*H+h
    gemm_k<false,false,false,false><<<dim3(8,1,BB*HH),256>>>(
        emtok, attention, nullptr, entatt, EE, LL, LL,
        (long long)EE*LL, (long long)LL*LL, (long long)EE*LL, HH,1,1);

    // 8) per-pair attention vectors + ctx_att
    pair_att_k<<<BB*PP, 64>>>(hts, emap, eatt, hatt, tatt);
    ctx_k<<<BB*PP, 256>>>(hts, entatt, ctx);

    // 9) h = t_att @ mention ; t = h_att @ mention   (512x768, K=48)
    gemm_k<false,false,false,false><<<dim3(12,8,BB),256>>>(
        tatt, mention, nullptr, h_, PP, DD, MM,
        (long long)PP*MM, (long long)MM*DD, (long long)PP*DD, 1,1,1);
    gemm_k<false,false,false,false><<<dim3(12,8,BB),256>>>(
        hatt, mention, nullptr, t_, PP, DD, MM,
        (long long)PP*MM, (long long)MM*DD, (long long)PP*DD, 1,1,1);

    // 10) context_info = ctx_att @ context   (512x768, K=512)
    gemm_k<false,false,false,false><<<dim3(12,8,BB),256>>>(
        ctx, context, nullptr, cinfo, PP, DD, LL,
        (long long)PP*LL, (long long)LL*DD, (long long)PP*DD, 1,1,1);

    // 11) hf = cinfo @ hcW^T + hcb ; tf = cinfo @ tcW^T + tcb   (2048x768, K=768)
    gemm_k<true,false,false,true><<<dim3(12,32,1),256>>>(
        cinfo, hcW, hcb, hf, BB*PP, DD, DD, 0,0,0, 1,1,1);
    gemm_k<true,false,false,true><<<dim3(12,32,1),256>>>(
        cinfo, tcW, tcb, tf, BB*PP, DD, DD, 0,0,0, 1,1,1);

    // 12) hf = tanh(h @ hW^T + hb + hf) ; tf = tanh(t @ tW^T + tb + tf)
    gemm_k<true,true,true,true><<<dim3(12,32,1),256>>>(
        h_, hW, hb, hf, BB*PP, DD, DD, 0,0,0, 1,1,1);
    gemm_k<true,true,true,true><<<dim3(12,32,1),256>>>(
        t_, tW, tb, tf, BB*PP, DD, DD, 0,0,0, 1,1,1);

    // 13) classifier: group-bilinear feat @ clasW^T + clasb
    cudaFuncSetAttribute(clas_k, cudaFuncAttributeMaxDynamicSharedMemorySize, CLAS_SMEM);
    clas_k<<<dim3(BB*PP/64, NBK), 256, CLAS_SMEM>>>(hf, tf, clasW, part);
    clas_red_k<<<(BB*PP*RR + 255)/256, 256>>>(part, clasb, out);
}

// round 3
// speedup vs baseline: 1.5212x; 1.5212x over previous
#include <cuda_runtime.h>
#include <cuda_bf16.h>
#include <cstdint>
#include <math.h>

// Problem constants
#define BB 4
#define LL 512
#define DD 768
#define HH 12
#define MM 48
#define EE 32
#define PP 512
#define RR 97
#define NBK 12      // D / 64 group blocks
#define NCH 24      // NBK * 2 (i-split)
#define KCLAS 49152 // D * 64

// ---------------- scratch (device globals; allocation-free) ----------------
__device__ float g_att_sum[BB*LL*LL];
__device__ float g_mention[BB*MM*DD];
__device__ float g_tmp1[BB*MM*LL];
__device__ float g_matt[BB*MM*MM];
__device__ float g_eatt[BB*EE*MM];
__device__ float g_emtok[BB*EE*LL];
__device__ float g_entatt[BB*HH*EE*LL];
__device__ float g_hatt[BB*PP*MM];
__device__ float g_tatt[BB*PP*MM];
__device__ float g_ctx[BB*PP*LL];
__device__ float g_h[BB*PP*DD];
__device__ float g_t[BB*PP*DD];
__device__ float g_cinfo[BB*PP*DD];
__device__ float g_hf[BB*PP*DD];
__device__ float g_tf[BB*PP*DD];
__device__ float g_part[NCH*BB*PP*RR];

// ---------------- tf32 helpers ----------------
static __device__ __forceinline__ uint32_t fu(float f) { return __float_as_uint(f); }

static __device__ __forceinline__ void split3(float x, uint32_t& h, uint32_t& l) {
    asm("cvt.rna.tf32.f32 %0, %1;" : "=r"(h) : "f"(x));
    float hf = __uint_as_float(h);
    float r = x - hf;
    asm("cvt.rna.tf32.f32 %0, %1;" : "=r"(l) : "f"(r));
}
static __device__ __forceinline__ void split3f(float x, float& hf, float& lf) {
    uint32_t h, l; split3(x, h, l);
    hf = __uint_as_float(h); lf = __uint_as_float(l);
}
static __device__ __forceinline__ void mma_tf32(float* c,
    uint32_t a0, uint32_t a1, uint32_t a2, uint32_t a3, uint32_t b0, uint32_t b1) {
    asm volatile(
        "mma.sync.aligned.m16n8k8.row.col.f32.tf32.tf32.f32 "
        "{%0,%1,%2,%3}, {%4,%5,%6,%7}, {%8,%9}, {%0,%1,%2,%3};"
        : "+f"(c[0]), "+f"(c[1]), "+f"(c[2]), "+f"(c[3])
        : "r"(a0), "r"(a1), "r"(a2), "r"(a3), "r"(b0), "r"(b1));
}

// ---------------- small kernels ----------------
__global__ void att_sum_k(const float* __restrict__ att, float* __restrict__ out)
{
    int idx = blockIdx.x * 256 + threadIdx.x;
    if (idx >= BB*LL*LL) return;
    int b  = idx >> 18;
    int lm = idx & (LL*LL - 1);
    const float* p = att + (size_t)b*HH*LL*LL + lm;
    float s = 0.f;
#pragma unroll
    for (int h = 0; h < HH; ++h) s += p[(size_t)h*LL*LL];
    out[idx] = s;
}

__global__ void rownorm_k(float* __restrict__ x)
{
    int row = blockIdx.x;
    float* p = x + (size_t)row * LL;
    int t = threadIdx.x;
    float v0 = p[t], v1 = p[t + 256];
    __shared__ float sm[256];
    sm[t] = v0 + v1; __syncthreads();
    for (int o = 128; o > 0; o >>= 1) { if (t < o) sm[t] += sm[t + o]; __syncthreads(); }
    float inv = 1.f / (sm[0] + 1e-30f);
    p[t] = v0 * inv; p[t + 256] = v1 * inv;
}

__global__ void pair_att_k(const int* __restrict__ hts,
                           const float* __restrict__ emap,
                           const float* __restrict__ eatt,
                           float* __restrict__ hattO, float* __restrict__ tattO)
{
    int bp = blockIdx.x;
    int b  = bp >> 9;
    int hi = hts[(size_t)bp*2], ti = hts[(size_t)bp*2 + 1];
    float mask = (hi + ti != 0) ? 1.f : 0.f;
    int t = threadIdx.x;
    float ha = 0.f, ta = 0.f;
    if (t < MM) {
        float hm = emap[((size_t)b*EE + hi)*MM + t] * mask;
        float tm = emap[((size_t)b*EE + ti)*MM + t] * mask;
        ha = eatt[((size_t)b*EE + hi)*MM + t] * tm;
        ta = eatt[((size_t)b*EE + ti)*MM + t] * hm;
    }
    __shared__ float smh[64], smt[64];
    smh[t] = ha; smt[t] = ta; __syncthreads();
    for (int o = 32; o > 0; o >>= 1) {
        if (t < o) { smh[t] += smh[t + o]; smt[t] += smt[t + o]; }
        __syncthreads();
    }
    float invh = 1.f / (smh[0] + 1e-30f);
    float invt = 1.f / (smt[0] + 1e-30f);
    if (t < MM) {
        hattO[(size_t)bp*MM + t] = ha * invh;
        tattO[(size_t)bp*MM + t] = ta * invt;
    }
}

__global__ void ctx_k(const int* __restrict__ hts,
                      const float* __restrict__ entatt,
                      float* __restrict__ ctxO)
{
    int bp = blockIdx.x; int b = bp >> 9;
    int hi = hts[(size_t)bp*2], ti = hts[(size_t)bp*2 + 1];
    float mask = (hi + ti != 0) ? 1.f : 0.f;
    int t = threadIdx.x;
    const float* base = entatt + (size_t)b*HH*EE*LL;
    float v0 = 0.f, v1 = 0.f;
#pragma unroll
    for (int h = 0; h < HH; ++h) {
        const float* ph = base + ((size_t)h*EE + hi)*LL;
        const float* pt = base + ((size_t)h*EE + ti)*LL;
        v0 += ph[t]       * pt[t];
        v1 += ph[t + 256] * pt[t + 256];
    }
    __shared__ float sm[256];
    sm[t] = v0 + v1; __syncthreads();
    for (int o = 128; o > 0; o >>= 1) { if (t < o) sm[t] += sm[t + o]; __syncthreads(); }
    float inv = mask / (sm[0] + 1e-30f);
    ctxO[(size_t)bp*LL + t]       = v0 * inv;
    ctxO[(size_t)bp*LL + t + 256] = v1 * inv;
}

// matt[b][m][j] = sum_k tmp1[b][m][k] * mmap[b][j][k]   (48x48, K=512)
__global__ void matt_k(const float* __restrict__ tmp1, const float* __restrict__ mmap,
                       float* __restrict__ matt)
{
    int blk = blockIdx.x;            // 0..BB*MM-1
    int b = blk / MM, m = blk % MM;
    __shared__ float srow[LL];
    int t = threadIdx.x;             // 64
    for (int v = t; v < LL; v += 64) srow[v] = tmp1[((size_t)b*MM + m)*LL + v];
    __syncthreads();
    if (t < MM) {
        const float* mr = mmap + ((size_t)b*MM + t)*LL;
        float s = 0.f;
#pragma unroll 8
        for (int k = 0; k < LL; ++k) s += srow[k] * mr[k];
        matt[(size_t)b*MM*MM + m*MM + t] = s;
    }
}

// eatt = emap @ matt (32x48, K=48)
__global__ void eatt_k(const float* __restrict__ emap, const float* __restrict__ matt,
                       float* __restrict__ eatt)
{
    int b = blockIdx.x;
    int idx = threadIdx.x;           // 256
    for (int v = idx; v < EE*MM; v += 256) {
        int e = v / MM, j = v % MM;
        float s = 0.f;
#pragma unroll
        for (int m = 0; m < MM; ++m)
            s += emap[((size_t)b*EE + e)*MM + m] * matt[(size_t)b*MM*MM + m*MM + j];
        eatt[(size_t)b*EE*MM + v] = s;
    }
}

// ---------------- generic FFMA GEMM (small steps) ----------------
template<bool TB>
__global__ __launch_bounds__(256)
void gemm_k(const float* __restrict__ Ag, const float* __restrict__ Bg,
            float* __restrict__ Cg,
            int M, int N, int K,
            long long sA, long long sB, long long sC,
            int dA, int dB, int dC)
{
    const int BM = 64, BN = 64, BK = 16;
    int z = blockIdx.z;
    const float* A  = Ag + (long long)(z / dA) * sA;
    const float* Bp = Bg + (long long)(z / dB) * sB;
    float*       C  = Cg + (long long)(z / dC) * sC;
    int row0 = blockIdx.y * BM;
    int col0 = blockIdx.x * BN;

    __shared__ float As[BK][BM + 1];
    __shared__ float Bs[BK][BN + 1];

    int tid = threadIdx.x;
    int tx = tid & 15, ty = tid >> 4;
    float acc[4][4] = {};

    for (int k0 = 0; k0 < K; k0 += BK) {
#pragma unroll
        for (int r = 0; r < 4; ++r) {
            int idx = tid + r * 256;
            int m = idx >> 4, k = idx & 15;
            float v = 0.f;
            if (row0 + m < M) v = A[(size_t)(row0 + m) * K + k0 + k];
            As[k][m] = v;
        }
        if (!TB) {
#pragma unroll
            for (int r = 0; r < 4; ++r) {
                int idx = tid + r * 256;
                int k = idx >> 6, n = idx & 63;
                float v = 0.f;
                if (col0 + n < N) v = Bp[(size_t)(k0 + k) * N + col0 + n];
                Bs[k][n] = v;
            }
        } else {
#pragma unroll
            for (int r = 0; r < 4; ++r) {
                int idx = tid + r * 256;
                int n = idx >> 4, k = idx & 15;
                float v = 0.f;
                if (col0 + n < N) v = Bp[(size_t)(col0 + n) * K + k0 + k];
                Bs[k][n] = v;
            }
        }
        __syncthreads();
#pragma unroll
        for (int k = 0; k < BK; ++k) {
            float a[4], bb[4];
#pragma unroll
            for (int i = 0; i < 4; ++i) a[i]  = As[k][ty * 4 + i];
#pragma unroll
            for (int j = 0; j < 4; ++j) bb[j] = Bs[k][tx * 4 + j];
#pragma unroll
            for (int i = 0; i < 4; ++i)
#pragma unroll
                for (int j = 0; j < 4; ++j) acc[i][j] += a[i] * bb[j];
        }
        __syncthreads();
    }

#pragma unroll
    for (int i = 0; i < 4; ++i) {
        int m = row0 + ty * 4 + i;
        if (m >= M) continue;
#pragma unroll
        for (int j = 0; j < 4; ++j) {
            int n = col0 + tx * 4 + j;
            if (n >= N) continue;
            C[(size_t)m * N + n] = acc[i][j];
        }
    }
}

// ---------------- tf32 (3x compensated) GEMM ----------------
// C = [tanh]( A1 @ B1^T(+) + [A2 @ B2^T] + bias1 + bias2 )
// TB=true : B row-major [N,K]; TB=false : B row-major [K,N]
// BM=128, BN=64, BK=32, 256 thr (8 warps: 4m x 2n, warp tile 32x32)
#define TF32_SMEM ((128*36*2 + 64*36*2) * 4)
template<bool TB, bool FUSE2, bool EPI>
__global__ __launch_bounds__(256)
void tf32gemm_k(const float* __restrict__ A1, const float* __restrict__ B1,
                const float* __restrict__ A2, const float* __restrict__ B2,
                const float* __restrict__ bias1, const float* __restrict__ bias2,
                float* __restrict__ Cg, int M, int N, int K,
                long long sA, long long sB, long long sC)
{
    extern __shared__ char smraw[];
    float* AsH = (float*)smraw;            // [128][36]
    float* AsL = AsH + 128*36;
    float* BsH = AsL + 128*36;             // [64][36]
    float* BsL = BsH + 64*36;

    int z = blockIdx.z;
    int row0 = blockIdx.y * 128, col0 = blockIdx.x * 64;
    int tid = threadIdx.x, lane = tid & 31, wid = tid >> 5;
    int m_off = (wid & 3) * 32, n_off = (wid >> 2) * 32;
    int l4 = lane >> 2, kq = lane & 3;

    float acc[2][4][4];
#pragma unroll
    for (int a = 0; a < 2; ++a)
#pragma unroll
        for (int b = 0; b < 4; ++b)
#pragma unroll
            for (int c = 0; c < 4; ++c) acc[a][b][c] = 0.f;

    const int NPASS = FUSE2 ? 2 : 1;
    for (int pass = 0; pass < NPASS; ++pass) {
        const float* A = (pass ? A2 : A1) + (long long)z * sA;
        const float* B = (pass ? B2 : B1) + (long long)z * sB;
        for (int k0 = 0; k0 < K; k0 += 32) {
            __syncthreads();
            // stage A tile 128x32
#pragma unroll
            for (int r2 = 0; r2 < 4; ++r2) {
                int slot = tid + r2 * 256;
                int m = slot >> 3, kk = (slot & 7) * 4;
                float4 v = *(const float4*)(A + (size_t)(row0 + m) * K + k0 + kk);
                float h, l;
                split3f(v.x, h, l); AsH[m*36+kk+0] = h; AsL[m*36+kk+0] = l;
                split3f(v.y, h, l); AsH[m*36+kk+1] = h; AsL[m*36+kk+1] = l;
                split3f(v.z, h, l); AsH[m*36+kk+2] = h; AsL[m*36+kk+2] = l;
                split3f(v.w, h, l); AsH[m*36+kk+3] = h; AsL[m*36+kk+3] = l;
            }
            // stage B tile 64x32 -> Bs[n][k]
            if (TB) {
#pragma unroll
                for (int r2 = 0; r2 < 2; ++r2) {
                    int slot = tid + r2 * 256;
                    int n = slot >> 3, kk = (slot & 7) * 4;
                    float4 v = *(const float4*)(B + (size_t)(col0 + n) * K + k0 + kk);
                    float h, l;
                    split3f(v.x, h, l); BsH[n*36+kk+0] = h; BsL[n*36+kk+0] = l;
                    split3f(v.y, h, l); BsH[n*36+kk+1] = h; BsL[n*36+kk+1] = l;
                    split3f(v.z, h, l); BsH[n*36+kk+2] = h; BsL[n*36+kk+2] = l;
                    split3f(v.w, h, l); BsH[n*36+kk+3] = h; BsL[n*36+kk+3] = l;
                }
            } else {
#pragma unroll
                for (int r2 = 0; r2 < 2; ++r2) {
                    int slot = tid + r2 * 256;
                    int k = slot >> 4, nq = (slot & 15) * 4;
                    float4 v = *(const float4*)(B + (size_t)(k0 + k) * N + col0 + nq);
                    float h, l;
                    split3f(v.x, h, l); BsH[(nq+0)*36+k] = h; BsL[(nq+0)*36+k] = l;
                    split3f(v.y, h, l); BsH[(nq+1)*36+k] = h; BsL[(nq+1)*36+k] = l;
                    split3f(v.z, h, l); BsH[(nq+2)*36+k] = h; BsL[(nq+2)*36+k] = l;
                    split3f(v.w, h, l); BsH[(nq+3)*36+k] = h; BsL[(nq+3)*36+k] = l;
                }
            }
            __syncthreads();
#pragma unroll
            for (int s = 0; s < 4; ++s) {
                int kb = s * 8 + kq;
                uint32_t aH[2][4], aL[2][4];
#pragma unroll
                for (int mt = 0; mt < 2; ++mt) {
                    int mr = m_off + mt*16 + l4;
                    aH[mt][0] = fu(AsH[mr*36+kb]);     aL[mt][0] = fu(AsL[mr*36+kb]);
                    aH[mt][1] = fu(AsH[(mr+8)*36+kb]); aL[mt][1] = fu(AsL[(mr+8)*36+kb]);
                    aH[mt][2] = fu(AsH[mr*36+kb+4]);   aL[mt][2] = fu(AsL[mr*36+kb+4]);
                    aH[mt][3] = fu(AsH[(mr+8)*36+kb+4]); aL[mt][3] = fu(AsL[(mr+8)*36+kb+4]);
                }
#pragma unroll
                for (int nt = 0; nt < 4; ++nt) {
                    int nr = n_off + nt*8 + l4;
                    uint32_t bH0 = fu(BsH[nr*36+kb]),   bH1 = fu(BsH[nr*36+kb+4]);
                    uint32_t bL0 = fu(BsL[nr*36+kb]),   bL1 = fu(BsL[nr*36+kb+4]);
#pragma unroll
                    for (int mt = 0; mt < 2; ++mt) {
                        mma_tf32(acc[mt][nt], aH[mt][0],aH[mt][1],aH[mt][2],aH[mt][3], bH0, bH1);
                        mma_tf32(acc[mt][nt], aH[mt][0],aH[mt][1],aH[mt][2],aH[mt][3], bL0, bL1);
                        mma_tf32(acc[mt][nt], aL[mt][0],aL[mt][1],aL[mt][2],aL[mt][3], bH0, bH1);
                    }
                }
            }
        }
    }

    float* C = Cg + (long long)z * sC;
#pragma unroll
    for (int mt = 0; mt < 2; ++mt) {
#pragma unroll
        for (int nt = 0; nt < 4; ++nt) {
            int mr = row0 + m_off + mt*16 + l4;
            int nc = col0 + n_off + nt*8 + 2*kq;
            float b0 = 0.f, b1 = 0.f;
            if (EPI) {
                b0 = bias1[nc]   + (FUSE2 ? bias2[nc]   : 0.f);
                b1 = bias1[nc+1] + (FUSE2 ? bias2[nc+1] : 0.f);
            }
            float v0 = acc[mt][nt][0] + b0;
            float v1 = acc[mt][nt][1] + b1;
            float v2 = acc[mt][nt][2] + b0;
            float v3 = acc[mt][nt][3] + b1;
            if (EPI) { v0 = tanhf(v0); v1 = tanhf(v1); v2 = tanhf(v2); v3 = tanhf(v3); }
            C[(size_t)mr * N + nc]       = v0;
            C[(size_t)mr * N + nc + 1]   = v1;
            C[(size_t)(mr+8) * N + nc]   = v2;
            C[(size_t)(mr+8) * N + nc+1] = v3;
        }
    }
}

// ---------------- classifier (group bilinear, tf32 3x MMA) ----------------
// part[n*2+z][p][r] = sum_{i in z-half, j} h[p,n*64+i] t[p,n*64+j] W[r, n*4096+i*64+j]
// block: 128 pairs x 112 (r pad) x (32 i, 64 j); 8 warps = 4m x 2n.
#define CLAS_SMEM ((128*33 + 8*128*4*2 + 2*8*112*4*2) * 4)
__global__ __launch_bounds__(256)
void clasmma_k(const float* __restrict__ Hf, const float* __restrict__ Tf,
               const float* __restrict__ W, float* __restrict__ part)
{
    extern __shared__ char smraw[];
    float* hs  = (float*)smraw;          // [128][33]
    float* tsS = hs + 128*33;            // float2[(s*128+p)*4+kq]  = 8192 floats
    float* wsH = tsS + 8192;             // float2[(s*112+r)*4+kq]  = 7168 floats
    float* wsL = wsH + 7168;

    const int n = blockIdx.y, z = blockIdx.z;
    const int p0 = blockIdx.x * 128;
    int tid = threadIdx.x, lane = tid & 31, wid = tid >> 5;
    int pbase = (wid & 3) * 32, nbase = (wid >> 2) * 56;
    int l4 = lane >> 2, kq = lane & 3;

    for (int v = tid; v < 128*32; v += 256) {
        int p = v >> 5, ii = v & 31;
        hs[p*33 + ii] = Hf[(size_t)(p0 + p)*DD + n*64 + z*32 + ii];
    }
    for (int v = tid; v < 128*64; v += 256) {
        int p = v >> 6, j = v & 63;
        float t = Tf[(size_t)(p0 + p)*DD + n*64 + j];
        int s = j >> 3, kq2 = j & 3, half = (j >> 2) & 1;
        tsS[(((s << 7) + p)*4 + kq2)*2 + half] = t;
    }
    for (int v = tid; v < 8*15*4*2; v += 256) {
        int half = v & 1, e = v >> 1;
        int kq2 = e & 3; e >>= 2;
        int r = 97 + (e % 15), s = e / 15;
        int fi = ((s*112 + r)*4 + kq2)*2 + half;
        wsH[fi] = 0.f; wsL[fi] = 0.f;
    }

    float acc[2][7][4];
#pragma unroll
    for (int a = 0; a < 2; ++a)
#pragma unroll
        for (int b = 0; b < 7; ++b)
#pragma unroll
            for (int c = 0; c < 4; ++c) acc[a][b][c] = 0.f;

    for (int ii = 0; ii < 32; ++ii) {
        int i = z*32 + ii;
        __syncthreads();
        for (int v = tid; v < RR*64; v += 256) {
            int r = v >> 6, j = v & 63;
            float w = W[(size_t)r*KCLAS + (size_t)n*4096 + i*64 + j];
            float wh, wl; split3f(w, wh, wl);
            int s = j >> 3, kq2 = j & 3, half = (j >> 2) & 1;
            int fi = ((s*112 + r)*4 + kq2)*2 + half;
            wsH[fi] = wh; wsL[fi] = wl;
        }
        __syncthreads();

        float hv0[2], hv1[2];
#pragma unroll
        for (int mt = 0; mt < 2; ++mt) {
            int pr = pbase + mt*16 + l4;
            hv0[mt] = hs[pr*33 + ii];
            hv1[mt] = hs[(pr+8)*33 + ii];
        }
        const float2* ts2 = (const float2*)tsS;
        const float2* wh2 = (const float2*)wsH;
        const float2* wl2 = (const float2*)wsL;
#pragma unroll
        for (int s = 0; s < 8; ++s) {
            uint32_t aH[2][4], aL[2][4];
#pragma unroll
            for (int mt = 0; mt < 2; ++mt) {
                int pr = pbase + mt*16 + l4;
                float2 ta = ts2[((s << 7) + pr)*4 + kq];
                float2 tb = ts2[((s << 7) + pr + 8)*4 + kq];
                split3(hv0[mt]*ta.x, aH[mt][0], aL[mt][0]);
                split3(hv1[mt]*tb.x, aH[mt][1], aL[mt][1]);
                split3(hv0[mt]*ta.y, aH[mt][2], aL[mt][2]);
                split3(hv1[mt]*tb.y, aH[mt][3], aL[mt][3]);
            }
#pragma unroll
            for (int nt = 0; nt < 7; ++nt) {
                int r = nbase + nt*8 + l4;
                float2 bh = wh2[(s*112 + r)*4 + kq];
                float2 bl = wl2[(s*112 + r)*4 + kq];
                uint32_t bH0 = fu(bh.x), bH1 = fu(bh.y);
                uint32_t bL0 = fu(bl.x), bL1 = fu(bl.y);
#pragma unroll
                for (int mt = 0; mt < 2; ++mt) {
                    mma_tf32(acc[mt][nt], aH[mt][0],aH[mt][1],aH[mt][2],aH[mt][3], bH0, bH1);
                    mma_tf32(acc[mt][nt], aH[mt][0],aH[mt][1],aH[mt][2],aH[mt][3], bL0, bL1);
                    mma_tf32(acc[mt][nt], aL[mt][0],aL[mt][1],aL[mt][2],aL[mt][3], bH0, bH1);
                }
            }
        }
    }

    int chunk = n*2 + z;
    float* po = part + (size_t)chunk * (BB*PP*RR);
#pragma unroll
    for (int mt = 0; mt < 2; ++mt) {
#pragma unroll
        for (int nt = 0; nt < 7; ++nt) {
            int p = p0 + pbase + mt*16 + l4;
            int r = nbase + nt*8 + 2*kq;
            if (r < RR)   po[(size_t)p*RR + r]       = acc[mt][nt][0];
            if (r+1 < RR) po[(size_t)p*RR + r + 1]   = acc[mt][nt][1];
            if (r < RR)   po[(size_t)(p+8)*RR + r]   = acc[mt][nt][2];
            if (r+1 < RR) po[(size_t)(p+8)*RR + r+1] = acc[mt][nt][3];
        }
    }
}

__global__ void clas_red_k(const float* __restrict__ part,
                           const float* __restrict__ clasb,
                           float* __restrict__ out)
{
    int idx = blockIdx.x * 256 + threadIdx.x;
    if (idx >= BB * PP * RR) return;
    int r = idx % RR;
    float s = clasb[r];
#pragma unroll
    for (int c = 0; c < NCH; ++c) s += part[(size_t)c * (BB * PP * RR) + idx];
    out[idx] = s;
}

// ---------------- host ----------------
extern "C" void kernel_launch(void* const* d_in, const int* in_sizes, int n_in,
                              void* d_out, int out_size)
{
    const float* context   = (const float*)d_in[0];
    const float* attention = (const float*)d_in[1];
    const float* mmap      = (const float*)d_in[2];
    const float* emap      = (const float*)d_in[3];
    const int*   hts       = (const int*)d_in[4];
    const float* hW   = (const float*)d_in[5];
    const float* hb   = (const float*)d_in[6];
    const float* tW   = (const float*)d_in[7];
    const float* tb   = (const float*)d_in[8];
    const float* hcW  = (const float*)d_in[9];
    const float* hcb  = (const float*)d_in[10];
    const float* tcW  = (const float*)d_in[11];
    const float* tcb  = (const float*)d_in[12];
    const float* clasW = (const float*)d_in[13];
    const float* clasb = (const float*)d_in[14];
    float* out = (float*)d_out;

    float *att_sum, *mention, *tmp1, *matt, *eatt, *emtok, *entatt;
    float *hatt, *tatt, *ctx, *h_, *t_, *cinfo, *hf, *tf, *part;
    cudaGetSymbolAddress((void**)&att_sum, g_att_sum);
    cudaGetSymbolAddress((void**)&mention, g_mention);
    cudaGetSymbolAddress((void**)&tmp1,    g_tmp1);
    cudaGetSymbolAddress((void**)&matt,    g_matt);
    cudaGetSymbolAddress((void**)&eatt,    g_eatt);
    cudaGetSymbolAddress((void**)&emtok,   g_emtok);
    cudaGetSymbolAddress((void**)&entatt,  g_entatt);
    cudaGetSymbolAddress((void**)&hatt,    g_hatt);
    cudaGetSymbolAddress((void**)&tatt,    g_tatt);
    cudaGetSymbolAddress((void**)&ctx,     g_ctx);
    cudaGetSymbolAddress((void**)&h_,      g_h);
    cudaGetSymbolAddress((void**)&t_,      g_t);
    cudaGetSymbolAddress((void**)&cinfo,   g_cinfo);
    cudaGetSymbolAddress((void**)&hf,      g_hf);
    cudaGetSymbolAddress((void**)&tf,      g_tf);
    cudaGetSymbolAddress((void**)&part,    g_part);

    cudaFuncSetAttribute(tf32gemm_k<true,true,true>,
                         cudaFuncAttributeMaxDynamicSharedMemorySize, TF32_SMEM);
    cudaFuncSetAttribute(tf32gemm_k<false,false,false>,
                         cudaFuncAttributeMaxDynamicSharedMemorySize, TF32_SMEM);
    cudaFuncSetAttribute(clasmma_k,
                         cudaFuncAttributeMaxDynamicSharedMemorySize, CLAS_SMEM);

    // 1) att_sum
    att_sum_k<<<(BB*LL*LL + 255)/256, 256>>>(attention, att_sum);

    // 2) mention = mention_map @ context
    gemm_k<false><<<dim3(12,1,BB),256>>>(
        mmap, context, mention, MM, DD, LL,
        (long long)MM*LL, (long long)LL*DD, (long long)MM*DD, 1,1,1);

    // 3) tmp1 = mention_map @ att_sum
    gemm_k<false><<<dim3(8,1,BB),256>>>(
        mmap, att_sum, tmp1, MM, LL, LL,
        (long long)MM*LL, (long long)LL*LL, (long long)MM*LL, 1,1,1);

    // 4) mention_att
    matt_k<<<BB*MM, 64>>>(tmp1, mmap, matt);

    // 5) entity_att
    eatt_k<<<BB, 256>>>(emap, matt, eatt);

    // 6) em_tok + normalize
    gemm_k<false><<<dim3(8,1,BB),256>>>(
        emap, mmap, emtok, EE, LL, MM,
        (long long)EE*MM, (long long)MM*LL, (long long)EE*LL, 1,1,1);
    rownorm_k<<<BB*EE, 256>>>(emtok);

    // 7) ent_att
    gemm_k<false><<<dim3(8,1,BB*HH),256>>>(
        emtok, attention, entatt, EE, LL, LL,
        (long long)EE*LL, (long long)LL*LL, (long long)EE*LL, HH,1,1);

    // 8) per-pair vectors
    pair_att_k<<<BB*PP, 64>>>(hts, emap, eatt, hatt, tatt);
    ctx_k<<<BB*PP, 256>>>(hts, entatt, ctx);

    // 9) h, t
    gemm_k<false><<<dim3(12,8,BB),256>>>(
        tatt, mention, h_, PP, DD, MM,
        (long long)PP*MM, (long long)MM*DD, (long long)PP*DD, 1,1,1);
    gemm_k<false><<<dim3(12,8,BB),256>>>(
        hatt, mention, t_, PP, DD, MM,
        (long long)PP*MM, (long long)MM*DD, (long long)PP*DD, 1,1,1);

    // 10) context_info = ctx @ context (tf32x3, NN, batched z=4)
    tf32gemm_k<false,false,false><<<dim3(12,4,BB),256,TF32_SMEM>>>(
        ctx, context, nullptr, nullptr, nullptr, nullptr,
        cinfo, PP, DD, LL,
        (long long)PP*LL, (long long)LL*DD, (long long)PP*DD);

    // 11+12) hf = tanh(h@hW^T + cinfo@hcW^T + hb + hcb); tf likewise
    tf32gemm_k<true,true,true><<<dim3(12,16,1),256,TF32_SMEM>>>(
        h_, hW, cinfo, hcW, hb, hcb, hf, BB*PP, DD, DD, 0,0,0);
    tf32gemm_k<true,true,true><<<dim3(12,16,1),256,TF32_SMEM>>>(
        t_, tW, cinfo, tcW, tb, tcb, tf, BB*PP, DD, DD, 0,0,0);

    // 13) classifier
    clasmma_k<<<dim3(BB*PP/128, NBK, 2), 256, CLAS_SMEM>>>(hf, tf, clasW, part);
    clas_red_k<<<(BB*PP*RR + 255)/256, 256>>>(part, clasb, out);
}